// round 2
// baseline (speedup 1.0000x reference)
#include <cuda_runtime.h>
#include <cstddef>

// Problem shapes (fixed for this problem instance)
#define BB   32
#define TT   8192
#define QD   512
#define VD   256
#define DD   128

#define TILE_T 128   // t-rows per score block
#define KC     16    // K chunk for score GEMM

// ---------------- device scratch (no allocation allowed) ----------------
__device__ float g_q[BB * DD];                 // projected query + bq
__device__ float g_score[BB * TT];             // raw additive scores (incl. bias)
__device__ float g_Spart[32][BB][VD];          // partial alignment@value per t-chunk
__device__ float g_S[BB * VD];                 // reduced alignment@value
__device__ float g_sumA[BB];                   // per-batch sum of alignment

// ---------------- f32x2 packed-FMA helpers (sm_100+) ----------------
__device__ __forceinline__ unsigned long long pack2(float lo, float hi) {
    unsigned long long r;
    asm("mov.b64 %0, {%1, %2};" : "=l"(r) : "f"(lo), "f"(hi));
    return r;
}
__device__ __forceinline__ void unpack2(unsigned long long v, float& lo, float& hi) {
    asm("mov.b64 {%0, %1}, %2;" : "=f"(lo), "=f"(hi) : "l"(v));
}
__device__ __forceinline__ void ffma2(unsigned long long& d,
                                      unsigned long long a,
                                      unsigned long long b) {
    asm("fma.rn.f32x2 %0, %1, %2, %0;" : "+l"(d) : "l"(a), "l"(b));
}

// ---------------- kernel A: q = query @ Wq + bq ----------------
__global__ void qproj_kernel(const float* __restrict__ query,
                             const float* __restrict__ Wq,
                             const float* __restrict__ bq) {
    int b = blockIdx.x;
    int d = threadIdx.x;           // 128 threads
    float acc = bq[d];
    const float* qr = query + (size_t)b * QD;
#pragma unroll 8
    for (int k = 0; k < QD; k++)
        acc += qr[k] * Wq[(size_t)k * DD + d];
    g_q[b * DD + d] = acc;
}

// ---------------- kernel B: fused v-GEMM + Bahdanau score ----------------
// score[b,t] = sum_d av[d] * tanh(q[b,d] + bv[d] + (value[b,t,:] @ Wv)[d]) + bias
__global__ __launch_bounds__(256) void score_kernel(
    const float* __restrict__ value,
    const float* __restrict__ Wv,
    const float* __restrict__ bv,
    const float* __restrict__ av,
    const float* __restrict__ sbias) {

    __shared__ __align__(16) float bsh[KC][DD];        // Wv chunk [k][d]
    __shared__ float vsh[KC][TILE_T + 1];              // value chunk, k-major [k][t]

    int b  = blockIdx.y;
    int t0 = blockIdx.x * TILE_T;
    int tid = threadIdx.x;
    int tx = tid & 15;             // 16 column groups (8 d-cols each)
    int ty = tid >> 4;             // 16 row groups   (8 t-rows each)

    unsigned long long acc[8][4];  // [row i][col pair j] packed fp32 pairs
#pragma unroll
    for (int i = 0; i < 8; i++)
#pragma unroll
        for (int j = 0; j < 4; j++) acc[i][j] = 0ull;

    const float* vptr = value + ((size_t)b * TT + t0) * VD;

    for (int kc = 0; kc < VD; kc += KC) {
        // load value tile 128t x 16k (transposed into smem)
#pragma unroll
        for (int r = 0; r < 2; r++) {
            int idx = tid + r * 256;             // 0..511 float4s
            int row = idx >> 2;
            int k4  = (idx & 3) * 4;
            float4 vv = *(const float4*)(vptr + (size_t)row * VD + kc + k4);
            vsh[k4 + 0][row] = vv.x;
            vsh[k4 + 1][row] = vv.y;
            vsh[k4 + 2][row] = vv.z;
            vsh[k4 + 3][row] = vv.w;
        }
        // load Wv chunk 16k x 128d
#pragma unroll
        for (int r = 0; r < 2; r++) {
            int idx = tid + r * 256;             // 0..511 float4s
            int kk  = idx >> 5;
            int d4  = (idx & 31) * 4;
            *(float4*)&bsh[kk][d4] = *(const float4*)(Wv + (size_t)(kc + kk) * DD + d4);
        }
        __syncthreads();

#pragma unroll
        for (int kk = 0; kk < KC; kk++) {
            unsigned long long ap[8];
#pragma unroll
            for (int i = 0; i < 8; i++) {
                float a = vsh[kk][ty * 8 + i];
                ap[i] = pack2(a, a);
            }
            unsigned long long bp[4];
#pragma unroll
            for (int j = 0; j < 4; j++)
                bp[j] = *(const unsigned long long*)&bsh[kk][tx * 8 + j * 2];
#pragma unroll
            for (int i = 0; i < 8; i++)
#pragma unroll
                for (int j = 0; j < 4; j++)
                    ffma2(acc[i][j], ap[i], bp[j]);
        }
        __syncthreads();
    }

    // epilogue: tanh + dot with attention_v, reduce across the 16 tx lanes
    float qv[8], avv[8];
#pragma unroll
    for (int j = 0; j < 8; j++) {
        int c = tx * 8 + j;
        qv[j]  = g_q[b * DD + c] + bv[c];
        avv[j] = av[c];
    }
    float part[8];
#pragma unroll
    for (int i = 0; i < 8; i++) {
        float s = 0.f;
#pragma unroll
        for (int j = 0; j < 4; j++) {
            float lo, hi;
            unpack2(acc[i][j], lo, hi);
            s += avv[2 * j]     * tanhf(qv[2 * j]     + lo);
            s += avv[2 * j + 1] * tanhf(qv[2 * j + 1] + hi);
        }
        part[i] = s;
    }
#pragma unroll
    for (int o = 8; o >= 1; o >>= 1)
#pragma unroll
        for (int i = 0; i < 8; i++)
            part[i] += __shfl_down_sync(0xffffffffu, part[i], o, 16);

    if (tx == 0) {
        float bias = *sbias;
#pragma unroll
        for (int i = 0; i < 8; i++)
            g_score[b * TT + t0 + ty * 8 + i] = part[i] + bias;
    }
}

// ---------------- kernel C: monotonic-attention scan ----------------
__device__ __forceinline__ float sigmoidf_stable(float s) {
    if (s >= 0.f) { float e = expf(-s); return 1.f / (1.f + e); }
    float e = expf(s); return e / (1.f + e);
}

__device__ float block_exscan256(float v, float* sm) {
    float x = v;
#pragma unroll
    for (int o = 1; o < 32; o <<= 1) {
        float y = __shfl_up_sync(0xffffffffu, x, o);
        if ((threadIdx.x & 31) >= o) x += y;
    }
    int warp = threadIdx.x >> 5;
    __syncthreads();                     // protect sm from previous use
    if ((threadIdx.x & 31) == 31) sm[warp] = x;
    __syncthreads();
    float woff = 0.f;
    for (int w = 0; w < warp; w++) woff += sm[w];
    return woff + x - v;                 // exclusive prefix
}

__global__ __launch_bounds__(256) void scan_kernel(
    const float* __restrict__ prev, float* __restrict__ out_align) {
    __shared__ float sm[8];
    const float TINYF = 1.17549435e-38f;
    int b = blockIdx.x;
    int tid = threadIdx.x;
    const float* sc = g_score + (size_t)b * TT;
    const float* pa = prev + (size_t)b * TT;
    int base = tid * 32;

    // phase 1: chunk sums of l = log(clip(1-p))
    float suml = 0.f;
    for (int c = 0; c < 32; c++) {
        float p  = sigmoidf_stable(sc[base + c]);
        float om = fminf(fmaxf(1.f - p, TINYF), 1.f);
        suml += logf(om);
    }
    float prefl = block_exscan256(suml, sm);

    // phase 2: chunk sums of u = prev / clip(cp)
    float run = 0.f, sumu = 0.f;
    for (int c = 0; c < 32; c++) {
        float p  = sigmoidf_stable(sc[base + c]);
        float om = fminf(fmaxf(1.f - p, TINYF), 1.f);
        float l  = logf(om);
        float cp = expf(prefl + run);    // exclusive cumsum of logs
        run += l;
        float u = pa[base + c] / fminf(fmaxf(cp, 1e-10f), 1.f);
        sumu += u;
    }
    float prefu = block_exscan256(sumu, sm);

    // phase 3: alignment = p * cp * inclusive_cumsum(u)
    run = 0.f;
    float runu = 0.f, suma = 0.f;
    for (int c = 0; c < 32; c++) {
        float p  = sigmoidf_stable(sc[base + c]);
        float om = fminf(fmaxf(1.f - p, TINYF), 1.f);
        float l  = logf(om);
        float cp = expf(prefl + run);
        run += l;
        float u = pa[base + c] / fminf(fmaxf(cp, 1e-10f), 1.f);
        runu += u;
        float al = p * cp * (prefu + runu);
        out_align[(size_t)b * TT + base + c] = al;
        suma += al;
    }
    float prefa = block_exscan256(suma, sm);
    if (tid == 255) g_sumA[b] = prefa + suma;
}

// ---------------- kernel D: partial S = alignment @ value (per t-chunk) ----------------
__global__ __launch_bounds__(256) void ctx_reduce_kernel(
    const float* __restrict__ value, const float* __restrict__ align) {
    __shared__ float ash[256];
    int tc = blockIdx.x;               // 32 t-chunks of 256
    int b  = blockIdx.y;
    int tid = threadIdx.x;
    int t0 = tc * 256;
    ash[tid] = align[(size_t)b * TT + t0 + tid];
    __syncthreads();
    const float* vp = value + ((size_t)b * TT + t0) * VD + tid;
    float acc = 0.f;
#pragma unroll 8
    for (int t = 0; t < 256; t++)
        acc += ash[t] * vp[(size_t)t * VD];
    g_Spart[tc][b][tid] = acc;         // plain store: deterministic
}

// ---------------- kernel E1: reduce partials ----------------
__global__ void ctx_sum_kernel() {
    int b = blockIdx.x;
    int k = threadIdx.x;               // 256
    float s = 0.f;
#pragma unroll
    for (int c = 0; c < 32; c++) s += g_Spart[c][b][k];
    g_S[b * VD + k] = s;
}

// ---------------- kernel E2: context = S @ Wv + sumA * bv ----------------
__global__ void ctx_final_kernel(const float* __restrict__ Wv,
                                 const float* __restrict__ bv,
                                 float* __restrict__ out_ctx) {
    int b = blockIdx.x;
    int d = threadIdx.x;               // 128
    float acc = g_sumA[b] * bv[d];
#pragma unroll 8
    for (int k = 0; k < VD; k++)
        acc += g_S[b * VD + k] * Wv[(size_t)k * DD + d];
    out_ctx[b * DD + d] = acc;
}

// ---------------- launcher ----------------
extern "C" void kernel_launch(void* const* d_in, const int* in_sizes, int n_in,
                              void* d_out, int out_size) {
    (void)in_sizes; (void)n_in; (void)out_size;
    const float* query = (const float*)d_in[0];
    const float* value = (const float*)d_in[1];
    const float* prev  = (const float*)d_in[2];
    const float* Wq    = (const float*)d_in[3];
    const float* bq    = (const float*)d_in[4];
    const float* Wv    = (const float*)d_in[5];
    const float* bv    = (const float*)d_in[6];
    const float* av    = (const float*)d_in[7];
    const float* sbias = (const float*)d_in[8];

    float* out       = (float*)d_out;
    float* out_ctx   = out;                  // [32, 128]
    float* out_align = out + BB * DD;        // [32, 8192]

    qproj_kernel<<<BB, DD>>>(query, Wq, bq);
    score_kernel<<<dim3(TT / TILE_T, BB), 256>>>(value, Wv, bv, av, sbias);
    scan_kernel<<<BB, 256>>>(prev, out_align);
    ctx_reduce_kernel<<<dim3(32, BB), 256>>>(value, out_align);
    ctx_sum_kernel<<<BB, VD>>>();
    ctx_final_kernel<<<BB, DD>>>(Wv, bv, out_ctx);
}